// round 12
// baseline (speedup 1.0000x reference)
#include <cuda_runtime.h>
#include <cuda_bf16.h>
#include <cstdint>

// ---------------------------------------------------------------------------
// MADPSNet via mma.sync bf16 (3-pass hi/lo error-compensated) GEMMs, v6.
//   v6: wave-quantization fix — L1/L3 CTAs each process MT=2 consecutive
//   m-tiles (grid 1024 -> 512 = 1.15 waves instead of 2.31 on 444 CTA
//   slots). Inner loop reverted to the R10 schedule (R11 hoist was neutral-
//   negative; scheduling is not the lever, the tail was).
//   Keeps: 64x128 CTA / 3 CTAs/SM, 3-stage cp.async, fused prepass,
//   bf16 hi/lo epilogue stores, split-K x2 L4 + deterministic reduce.
// ---------------------------------------------------------------------------

#define NUM_AGENTS 8
#define BATCH      2048
typedef __nv_bfloat16 bf16;

// ---------------- scratch (__device__ globals) ----------------------------
__device__ bf16 g_inh[NUM_AGENTS * BATCH * 256];
__device__ bf16 g_inl[NUM_AGENTS * BATCH * 256];
__device__ bf16 g_y1h[NUM_AGENTS * BATCH * 512];
__device__ bf16 g_y1l[NUM_AGENTS * BATCH * 512];
__device__ bf16 g_y2h[NUM_AGENTS * BATCH * 256];
__device__ bf16 g_y2l[NUM_AGENTS * BATCH * 256];
__device__ bf16 g_y3h[NUM_AGENTS * BATCH * 512];
__device__ bf16 g_y3l[NUM_AGENTS * BATCH * 512];
__device__ float g_p4[2 * NUM_AGENTS * BATCH * 128];   // L4 split-K partials

__device__ bf16 g_w1h[NUM_AGENTS * 256 * 512];
__device__ bf16 g_w1l[NUM_AGENTS * 256 * 512];
__device__ bf16 g_w2h[NUM_AGENTS * 512 * 256];
__device__ bf16 g_w2l[NUM_AGENTS * 512 * 256];
__device__ bf16 g_w3h[NUM_AGENTS * 256 * 512];
__device__ bf16 g_w3l[NUM_AGENTS * 256 * 512];
__device__ bf16 g_w4h[NUM_AGENTS * 512 * 128];
__device__ bf16 g_w4l[NUM_AGENTS * 512 * 128];

// ---------------- helpers --------------------------------------------------
__device__ __forceinline__ uint32_t smem_u32(const void* p) {
    uint32_t a;
    asm("{ .reg .u64 t; cvta.to.shared.u64 t, %1; cvt.u32.u64 %0, t; }" : "=r"(a) : "l"(p));
    return a;
}
__device__ __forceinline__ void ldsm4(uint32_t (&r)[4], uint32_t addr) {
    asm volatile("ldmatrix.sync.aligned.m8n8.x4.shared.b16 {%0,%1,%2,%3}, [%4];"
                 : "=r"(r[0]), "=r"(r[1]), "=r"(r[2]), "=r"(r[3]) : "r"(addr));
}
__device__ __forceinline__ void ldsm4t(uint32_t (&r)[4], uint32_t addr) {
    asm volatile("ldmatrix.sync.aligned.m8n8.x4.trans.shared.b16 {%0,%1,%2,%3}, [%4];"
                 : "=r"(r[0]), "=r"(r[1]), "=r"(r[2]), "=r"(r[3]) : "r"(addr));
}
__device__ __forceinline__ void mma_bf16(float (&d)[4], const uint32_t (&a)[4],
                                         uint32_t b0, uint32_t b1) {
    asm volatile(
        "mma.sync.aligned.m16n8k16.row.col.f32.bf16.bf16.f32 "
        "{%0,%1,%2,%3}, {%4,%5,%6,%7}, {%8,%9}, {%0,%1,%2,%3};"
        : "+f"(d[0]), "+f"(d[1]), "+f"(d[2]), "+f"(d[3])
        : "r"(a[0]), "r"(a[1]), "r"(a[2]), "r"(a[3]), "r"(b0), "r"(b1));
}
__device__ __forceinline__ void cp16(uint32_t dst, const void* src) {
    asm volatile("cp.async.cg.shared.global [%0], [%1], 16;" :: "r"(dst), "l"(src));
}
template <int NW>
__device__ __forceinline__ void cp_wait() {
    asm volatile("cp.async.wait_group %0;" :: "n"(NW));
}
#define CP_COMMIT() asm volatile("cp.async.commit_group;" ::: "memory")

__device__ __forceinline__ float bfr(float x) {
    return __bfloat162float(__float2bfloat16_rn(x));
}
__device__ __forceinline__ uint32_t pack2bf(float a, float b) {
    __nv_bfloat162 t = __floats2bfloat162_rn(a, b);
    return *reinterpret_cast<uint32_t*>(&t);
}
// A-tile swizzle: rows x 32 bf16 (64B rows)
__device__ __forceinline__ uint32_t swa(int row, int c16) {
    return (uint32_t)(row * 64 + (((c16) ^ ((row >> 1) & 3)) << 4));
}

// ---------------- fused prepass: elementwise bf16 hi/lo splits -------------
__global__ void __launch_bounds__(256)
prep_kernel(const float* __restrict__ Ws1, const float* __restrict__ Ws2,
            const float* __restrict__ Wd1, const float* __restrict__ Wd2,
            const float* __restrict__ inputs,
            const int* __restrict__ sel_s, const int* __restrict__ sel_d,
            bf16* __restrict__ w1h, bf16* __restrict__ w1l,
            bf16* __restrict__ w2h, bf16* __restrict__ w2l,
            bf16* __restrict__ w3h, bf16* __restrict__ w3l,
            bf16* __restrict__ w4h, bf16* __restrict__ w4l,
            bf16* __restrict__ inh, bf16* __restrict__ inl)
{
    const int seg = blockIdx.y;
    const int ag  = blockIdx.z;
    const float* src;
    bf16 *oh, *ol;
    int n4;
    int e;
    switch (seg) {
    case 0:
        e = sel_s[ag]; e = e < 0 ? 0 : (e > 7 ? 7 : e);
        src = Ws1 + (size_t)e * 131072; oh = w1h + (size_t)ag * 131072;
        ol = w1l + (size_t)ag * 131072; n4 = 32768; break;
    case 1:
        e = sel_s[ag]; e = e < 0 ? 0 : (e > 7 ? 7 : e);
        src = Ws2 + (size_t)e * 131072; oh = w2h + (size_t)ag * 131072;
        ol = w2l + (size_t)ag * 131072; n4 = 32768; break;
    case 2:
        e = sel_d[ag]; e = e < 0 ? 0 : (e > 7 ? 7 : e);
        src = Wd1 + (size_t)e * 131072; oh = w3h + (size_t)ag * 131072;
        ol = w3l + (size_t)ag * 131072; n4 = 32768; break;
    case 3:
        e = sel_d[ag]; e = e < 0 ? 0 : (e > 7 ? 7 : e);
        src = Wd2 + (size_t)e * 65536;  oh = w4h + (size_t)ag * 65536;
        ol = w4l + (size_t)ag * 65536;  n4 = 16384; break;
    default:
        src = inputs + (size_t)ag * 524288; oh = inh + (size_t)ag * 524288;
        ol = inl + (size_t)ag * 524288; n4 = 131072; break;
    }
    for (int i = blockIdx.x * 256 + threadIdx.x; i < n4; i += 32 * 256) {
        float4 v = ((const float4*)src)[i];
        float h0 = bfr(v.x), h1 = bfr(v.y), h2 = bfr(v.z), h3 = bfr(v.w);
        ((uint2*)oh)[i] = make_uint2(pack2bf(h0, h1), pack2bf(h2, h3));
        ((uint2*)ol)[i] = make_uint2(pack2bf(v.x - h0, v.y - h1),
                                     pack2bf(v.z - h2, v.w - h3));
    }
}

// ---------------- main GEMM ------------------------------------------------
// CTA tile 64m x 128n, 8 warps (2m x 4n, warp tile 32x32), BK=32, 3-stage
// cp.async. Stage layout: Ah 4KB | Al 4KB | Bh 8KB | Bl 8KB = 24KB.
// MT = consecutive m-tiles per CTA (wave-quantization control).
// OMODE: 0 = fp32 out + bias, 1 = bf16 hi/lo out + bias, 2 = raw partial.
// K = per-k-group depth, KROW = full A row stride (weight per-agent stride
// is KROW*N). blockIdx.x encodes (kgroup, n-tile): kg = bx/(N/128).
template <int K, int KROW, int N, bool RELU, int OMODE, int MT>
__global__ void __launch_bounds__(256, 3)
gemm_mma_kernel(const bf16* __restrict__ AH, const bf16* __restrict__ AL,
                const bf16* __restrict__ WH, const bf16* __restrict__ WL,
                const float* __restrict__ Ball,
                float* __restrict__ Out,
                bf16* __restrict__ Oh, bf16* __restrict__ Ol,
                const int* __restrict__ sel)
{
    extern __shared__ __align__(1024) char smem[];
    const uint32_t sb = smem_u32(smem);

    const int tid  = threadIdx.x;
    const int wid  = tid >> 5;
    const int lane = tid & 31;

    const int ag = blockIdx.z;
    int e = sel[ag]; e = e < 0 ? 0 : (e > 7 ? 7 : e);

    const int NX = N / 128;
    const int kg = blockIdx.x / NX;
    const int bn = (blockIdx.x % NX) * 128;

    const bf16* Ah_ = AH + (size_t)ag * BATCH * KROW + (size_t)kg * K;
    const bf16* Al_ = AL + (size_t)ag * BATCH * KROW + (size_t)kg * K;
    const bf16* Bh_ = WH + (size_t)ag * KROW * N + (size_t)kg * K * N;
    const bf16* Bl_ = WL + (size_t)ag * KROW * N + (size_t)kg * K * N;
    const float* bp = Ball + (size_t)e * N;

    // smem: [0..512) bias fp32, [1024..) 3 x 24KB stage buffers
    if (OMODE != 2 && tid < 128) ((float*)smem)[tid] = bp[bn + tid];

    const int m0 = (wid >> 2) * 32;   // 2 m-groups
    const int n0 = (wid & 3) * 32;    // 4 n-groups

    const int lrow = lane & 15, lqh = lane >> 4;
    uint32_t aA[2];
#pragma unroll
    for (int mt = 0; mt < 2; mt++)
        aA[mt] = sb + 1024 + swa(m0 + mt * 16 + lrow, lqh);
    const int kr = (lane & 7) + ((lane >> 3) & 1) * 8;
    uint32_t bB[2];
#pragma unroll
    for (int g = 0; g < 2; g++) {
        int nch = ((n0 + g * 16) >> 3) + (lane >> 4);
        bB[g] = sb + 1024 + 8192 + kr * 256 + ((uint32_t)(nch ^ (kr & 7)) << 4);
    }

    const int NC = K / 32;

    auto ISSUE = [&](int c, int bm) {
        const int k0 = c * 32;
        const uint32_t s = sb + 1024 + (uint32_t)(c % 3) * 24576u;
        // A: 64 rows x 4 chunks(16B) = 256 chunks; 1/thread for h and l
        {
            int r = tid >> 2, cq = tid & 3;
            size_t go = (size_t)(bm + r) * KROW + k0 + cq * 8;
            uint32_t ad = swa(r, cq);
            cp16(s + ad,        Ah_ + go);
            cp16(s + 4096 + ad, Al_ + go);
        }
        // B: 32 k-rows x 16 chunks(16B) = 512; 2/thread for h and l
#pragma unroll
        for (int i = 0; i < 2; i++) {
            int fid = i * 256 + tid;
            int r = fid >> 4, cq = fid & 15;
            size_t go = (size_t)(k0 + r) * N + bn + cq * 8;
            uint32_t ad = (uint32_t)(r * 256 + ((cq ^ (r & 7)) << 4));
            cp16(s + 8192 + ad,  Bh_ + go);
            cp16(s + 16384 + ad, Bl_ + go);
        }
        CP_COMMIT();
    };

    const float* bias = (const float*)smem;
    float* Cp  = (OMODE == 0) ? (Out + (size_t)ag * BATCH * N) : nullptr;
    float* Pp  = (OMODE == 2) ? (Out + ((size_t)kg * NUM_AGENTS + ag) * BATCH * N) : nullptr;
    bf16* OhP  = (OMODE == 1) ? (Oh + (size_t)ag * BATCH * N) : nullptr;
    bf16* OlP  = (OMODE == 1) ? (Ol + (size_t)ag * BATCH * N) : nullptr;

    for (int it = 0; it < MT; it++) {
        const int bm = (blockIdx.y * MT + it) * 64;
        // barrier: all warps done consuming previous tile's stage buffers
        __syncthreads();
        ISSUE(0, bm);
        ISSUE(1, bm);

        float acc[2][4][4];
#pragma unroll
        for (int mt = 0; mt < 2; mt++)
#pragma unroll
            for (int nt = 0; nt < 4; nt++)
#pragma unroll
                for (int j = 0; j < 4; j++) acc[mt][nt][j] = 0.0f;

        for (int c = 0; c < NC; c++) {
            if (c + 1 < NC) cp_wait<1>(); else cp_wait<0>();
            __syncthreads();
            if (c + 2 < NC) ISSUE(c + 2, bm);

            const uint32_t stg = (uint32_t)(c % 3) * 24576u;
#pragma unroll
            for (int ks = 0; ks < 2; ks++) {
                uint32_t ah[2][4], al[2][4];
#pragma unroll
                for (int mt = 0; mt < 2; mt++) {
                    uint32_t ad = (aA[mt] + stg) ^ ((uint32_t)ks << 5);
                    ldsm4(ah[mt], ad);
                    ldsm4(al[mt], ad + 4096);
                }
#pragma unroll
                for (int g = 0; g < 2; g++) {
                    uint32_t bh[4], bl[4];
                    uint32_t bd = bB[g] + stg + (uint32_t)ks * 4096u;
                    ldsm4t(bh, bd);
                    ldsm4t(bl, bd + 8192);
#pragma unroll
                    for (int mt = 0; mt < 2; mt++) {
                        const int nt = g * 2;
                        mma_bf16(acc[mt][nt],     ah[mt], bh[0], bh[1]);
                        mma_bf16(acc[mt][nt + 1], ah[mt], bh[2], bh[3]);
                        mma_bf16(acc[mt][nt],     ah[mt], bl[0], bl[1]);
                        mma_bf16(acc[mt][nt + 1], ah[mt], bl[2], bl[3]);
                        mma_bf16(acc[mt][nt],     al[mt], bh[0], bh[1]);
                        mma_bf16(acc[mt][nt + 1], al[mt], bh[2], bh[3]);
                    }
                }
            }
        }

        // ---- epilogue for this m-tile ----
#pragma unroll
        for (int mt = 0; mt < 2; mt++) {
            const int mrow = bm + m0 + mt * 16 + (lane >> 2);
#pragma unroll
            for (int nt = 0; nt < 4; nt++) {
                const int nc = n0 + nt * 8 + 2 * (lane & 3);
                float o0 = acc[mt][nt][0], o1 = acc[mt][nt][1];
                float o2 = acc[mt][nt][2], o3 = acc[mt][nt][3];
                if (OMODE != 2) {
                    const float b0 = bias[nc], b1 = bias[nc + 1];
                    o0 += b0; o1 += b1; o2 += b0; o3 += b1;
                }
                if (RELU) {
                    o0 = fmaxf(o0, 0.f); o1 = fmaxf(o1, 0.f);
                    o2 = fmaxf(o2, 0.f); o3 = fmaxf(o3, 0.f);
                }
                const size_t i0 = (size_t)mrow * N + bn + nc;
                const size_t i1 = (size_t)(mrow + 8) * N + bn + nc;
                if (OMODE == 1) {
                    float h0 = bfr(o0), h1 = bfr(o1), h2 = bfr(o2), h3 = bfr(o3);
                    *(uint32_t*)(OhP + i0) = pack2bf(h0, h1);
                    *(uint32_t*)(OlP + i0) = pack2bf(o0 - h0, o1 - h1);
                    *(uint32_t*)(OhP + i1) = pack2bf(h2, h3);
                    *(uint32_t*)(OlP + i1) = pack2bf(o2 - h2, o3 - h3);
                } else if (OMODE == 0) {
                    *(float2*)(Cp + i0) = make_float2(o0, o1);
                    *(float2*)(Cp + i1) = make_float2(o2, o3);
                } else {
                    *(float2*)(Pp + i0) = make_float2(o0, o1);
                    *(float2*)(Pp + i1) = make_float2(o2, o3);
                }
            }
        }
    }
}

// ---------------- split-K reduce: out = p0 + p1 + bias ---------------------
__global__ void __launch_bounds__(256)
reduce4_kernel(const float* __restrict__ P, const float* __restrict__ Ball,
               const int* __restrict__ sel_d, float* __restrict__ out)
{
    const int i = blockIdx.x * 256 + threadIdx.x;          // float4 index
    const float4 a = ((const float4*)P)[i];
    const float4 b = ((const float4*)P)[i + 524288];
    const int e4 = i * 4;
    const int ag = e4 >> 18;                               // / (2048*128)
    int e = sel_d[ag]; e = e < 0 ? 0 : (e > 7 ? 7 : e);
    const float4 bb = *(const float4*)(Ball + e * 128 + (e4 & 127));
    ((float4*)out)[i] = make_float4(a.x + b.x + bb.x, a.y + b.y + bb.y,
                                    a.z + b.z + bb.z, a.w + b.w + bb.w);
}

// ---------------------------------------------------------------------------
extern "C" void kernel_launch(void* const* d_in, const int* in_sizes, int n_in,
                              void* d_out, int out_size)
{
    const float* inputs = (const float*)d_in[0];
    const int*   sel_s  = (const int*)d_in[1];
    const int*   sel_d  = (const int*)d_in[2];
    const float* Ws1 = (const float*)d_in[3];
    const float* bs1 = (const float*)d_in[4];
    const float* Ws2 = (const float*)d_in[5];
    const float* bs2 = (const float*)d_in[6];
    const float* Wd1 = (const float*)d_in[7];
    const float* bd1 = (const float*)d_in[8];
    const float* Wd2 = (const float*)d_in[9];
    const float* bd2 = (const float*)d_in[10];
    float* out = (float*)d_out;

    void* p;
    bf16 *inh, *inl, *y1h, *y1l, *y2h, *y2l, *y3h, *y3l;
    float* p4;
    cudaGetSymbolAddress(&p, g_inh); inh = (bf16*)p;
    cudaGetSymbolAddress(&p, g_inl); inl = (bf16*)p;
    cudaGetSymbolAddress(&p, g_y1h); y1h = (bf16*)p;
    cudaGetSymbolAddress(&p, g_y1l); y1l = (bf16*)p;
    cudaGetSymbolAddress(&p, g_y2h); y2h = (bf16*)p;
    cudaGetSymbolAddress(&p, g_y2l); y2l = (bf16*)p;
    cudaGetSymbolAddress(&p, g_y3h); y3h = (bf16*)p;
    cudaGetSymbolAddress(&p, g_y3l); y3l = (bf16*)p;
    cudaGetSymbolAddress(&p, g_p4);  p4  = (float*)p;
    bf16 *w1h, *w1l, *w2h, *w2l, *w3h, *w3l, *w4h, *w4l;
    cudaGetSymbolAddress(&p, g_w1h); w1h = (bf16*)p;
    cudaGetSymbolAddress(&p, g_w1l); w1l = (bf16*)p;
    cudaGetSymbolAddress(&p, g_w2h); w2h = (bf16*)p;
    cudaGetSymbolAddress(&p, g_w2l); w2l = (bf16*)p;
    cudaGetSymbolAddress(&p, g_w3h); w3h = (bf16*)p;
    cudaGetSymbolAddress(&p, g_w3l); w3l = (bf16*)p;
    cudaGetSymbolAddress(&p, g_w4h); w4h = (bf16*)p;
    cudaGetSymbolAddress(&p, g_w4l); w4l = (bf16*)p;

    const int SMEM_BYTES = 1024 + 3 * 24576;   // 74752
    // Three distinct instantiations (L1 and L3 share one); each needs opt-in.
    cudaFuncSetAttribute(gemm_mma_kernel<256, 256, 512, true,  1, 2>,
                         cudaFuncAttributeMaxDynamicSharedMemorySize, SMEM_BYTES);
    cudaFuncSetAttribute(gemm_mma_kernel<512, 512, 256, true,  1, 1>,
                         cudaFuncAttributeMaxDynamicSharedMemorySize, SMEM_BYTES);
    cudaFuncSetAttribute(gemm_mma_kernel<256, 512, 128, false, 2, 1>,
                         cudaFuncAttributeMaxDynamicSharedMemorySize, SMEM_BYTES);

    prep_kernel<<<dim3(32, 5, 8), 256>>>(Ws1, Ws2, Wd1, Wd2, inputs, sel_s, sel_d,
                                         w1h, w1l, w2h, w2l, w3h, w3l, w4h, w4l,
                                         inh, inl);

    dim3 blk(256);
    // L1/L3: MT=2 -> grid 512 CTAs (1.15 waves on 444 slots, was 2.31)
    gemm_mma_kernel<256, 256, 512, true,  1, 2><<<dim3(4, 16, 8), blk, SMEM_BYTES>>>(
        inh, inl, w1h, w1l, bs1, nullptr, y1h, y1l, sel_s);
    gemm_mma_kernel<512, 512, 256, true,  1, 1><<<dim3(2, 32, 8), blk, SMEM_BYTES>>>(
        y1h, y1l, w2h, w2l, bs2, nullptr, y2h, y2l, sel_s);
    gemm_mma_kernel<256, 256, 512, true,  1, 2><<<dim3(4, 16, 8), blk, SMEM_BYTES>>>(
        y2h, y2l, w3h, w3l, bd1, nullptr, y3h, y3l, sel_d);
    // L4: split-K x2 -> raw partials, then deterministic reduce (+bias)
    gemm_mma_kernel<256, 512, 128, false, 2, 1><<<dim3(2, 32, 8), blk, SMEM_BYTES>>>(
        y3h, y3l, w4h, w4l, bd2, p4, nullptr, nullptr, sel_d);
    reduce4_kernel<<<2048, 256>>>(p4, bd2, sel_d, out);
}

// round 13
// speedup vs baseline: 1.5533x; 1.5533x over previous
#include <cuda_runtime.h>
#include <cuda_fp16.h>
#include <cstdint>

// ---------------------------------------------------------------------------
// MADPSNet via mma.sync fp16 2-pass asymmetric-precision GEMMs, v7.
//   Evidence (R9-R12): all schedules converge to ~294 TF/s = the legacy
//   mma.sync HMMA structural rate -> we are AT the roofline; only pass-count
//   reduction helps. v7: A (activations) = single fp16 (2^-12 rounding,
//   values ~N(0,1)); B (weights) = fp16 hi+lo (~22-bit, exact enough).
//   2 MMA passes (a*bh + a*bl) instead of 3 -> 2/3 the MMA work.
//   Error budget: 4 fp16 activation roundings, ~2.8e-4 total (vs 1e-3 gate).
//   Keeps R10 config: 64x128 CTA, 3 CTAs/SM, 3-stage cp.async, fused
//   prepass, split-K x2 L4 + deterministic reduce.
// ---------------------------------------------------------------------------

#define NUM_AGENTS 8
#define BATCH      2048
typedef __half f16;

// ---------------- scratch (__device__ globals) ----------------------------
__device__ f16 g_inq[NUM_AGENTS * BATCH * 256];     // fp16 input
__device__ f16 g_y1[NUM_AGENTS * BATCH * 512];      // fp16 activations
__device__ f16 g_y2[NUM_AGENTS * BATCH * 256];
__device__ f16 g_y3[NUM_AGENTS * BATCH * 512];
__device__ float g_p4[2 * NUM_AGENTS * BATCH * 128];   // L4 split-K partials

__device__ f16 g_w1h[NUM_AGENTS * 256 * 512];
__device__ f16 g_w1l[NUM_AGENTS * 256 * 512];
__device__ f16 g_w2h[NUM_AGENTS * 512 * 256];
__device__ f16 g_w2l[NUM_AGENTS * 512 * 256];
__device__ f16 g_w3h[NUM_AGENTS * 256 * 512];
__device__ f16 g_w3l[NUM_AGENTS * 256 * 512];
__device__ f16 g_w4h[NUM_AGENTS * 512 * 128];
__device__ f16 g_w4l[NUM_AGENTS * 512 * 128];

// ---------------- helpers --------------------------------------------------
__device__ __forceinline__ uint32_t smem_u32(const void* p) {
    uint32_t a;
    asm("{ .reg .u64 t; cvta.to.shared.u64 t, %1; cvt.u32.u64 %0, t; }" : "=r"(a) : "l"(p));
    return a;
}
__device__ __forceinline__ void ldsm4(uint32_t (&r)[4], uint32_t addr) {
    asm volatile("ldmatrix.sync.aligned.m8n8.x4.shared.b16 {%0,%1,%2,%3}, [%4];"
                 : "=r"(r[0]), "=r"(r[1]), "=r"(r[2]), "=r"(r[3]) : "r"(addr));
}
__device__ __forceinline__ void ldsm4t(uint32_t (&r)[4], uint32_t addr) {
    asm volatile("ldmatrix.sync.aligned.m8n8.x4.trans.shared.b16 {%0,%1,%2,%3}, [%4];"
                 : "=r"(r[0]), "=r"(r[1]), "=r"(r[2]), "=r"(r[3]) : "r"(addr));
}
__device__ __forceinline__ void mma_f16(float (&d)[4], const uint32_t (&a)[4],
                                        uint32_t b0, uint32_t b1) {
    asm volatile(
        "mma.sync.aligned.m16n8k16.row.col.f32.f16.f16.f32 "
        "{%0,%1,%2,%3}, {%4,%5,%6,%7}, {%8,%9}, {%0,%1,%2,%3};"
        : "+f"(d[0]), "+f"(d[1]), "+f"(d[2]), "+f"(d[3])
        : "r"(a[0]), "r"(a[1]), "r"(a[2]), "r"(a[3]), "r"(b0), "r"(b1));
}
__device__ __forceinline__ void cp16(uint32_t dst, const void* src) {
    asm volatile("cp.async.cg.shared.global [%0], [%1], 16;" :: "r"(dst), "l"(src));
}
template <int NW>
__device__ __forceinline__ void cp_wait() {
    asm volatile("cp.async.wait_group %0;" :: "n"(NW));
}
#define CP_COMMIT() asm volatile("cp.async.commit_group;" ::: "memory")

__device__ __forceinline__ float h16r(float x) {          // round to fp16, exact fp32
    return __half2float(__float2half_rn(x));
}
__device__ __forceinline__ uint32_t pack2h(float a, float b) {
    __half2 t = __floats2half2_rn(a, b);
    return *reinterpret_cast<uint32_t*>(&t);
}
// A-tile swizzle: rows x 32 fp16 (64B rows)
__device__ __forceinline__ uint32_t swa(int row, int c16) {
    return (uint32_t)(row * 64 + (((c16) ^ ((row >> 1) & 3)) << 4));
}

// ---------------- fused prepass --------------------------------------------
// seg 0..3: weights -> fp16 hi/lo. seg 4: input -> single fp16.
__global__ void __launch_bounds__(256)
prep_kernel(const float* __restrict__ Ws1, const float* __restrict__ Ws2,
            const float* __restrict__ Wd1, const float* __restrict__ Wd2,
            const float* __restrict__ inputs,
            const int* __restrict__ sel_s, const int* __restrict__ sel_d,
            f16* __restrict__ w1h, f16* __restrict__ w1l,
            f16* __restrict__ w2h, f16* __restrict__ w2l,
            f16* __restrict__ w3h, f16* __restrict__ w3l,
            f16* __restrict__ w4h, f16* __restrict__ w4l,
            f16* __restrict__ inq)
{
    const int seg = blockIdx.y;
    const int ag  = blockIdx.z;
    const float* src;
    f16 *oh, *ol;
    int n4;
    int e;
    switch (seg) {
    case 0:
        e = sel_s[ag]; e = e < 0 ? 0 : (e > 7 ? 7 : e);
        src = Ws1 + (size_t)e * 131072; oh = w1h + (size_t)ag * 131072;
        ol = w1l + (size_t)ag * 131072; n4 = 32768; break;
    case 1:
        e = sel_s[ag]; e = e < 0 ? 0 : (e > 7 ? 7 : e);
        src = Ws2 + (size_t)e * 131072; oh = w2h + (size_t)ag * 131072;
        ol = w2l + (size_t)ag * 131072; n4 = 32768; break;
    case 2:
        e = sel_d[ag]; e = e < 0 ? 0 : (e > 7 ? 7 : e);
        src = Wd1 + (size_t)e * 131072; oh = w3h + (size_t)ag * 131072;
        ol = w3l + (size_t)ag * 131072; n4 = 32768; break;
    case 3:
        e = sel_d[ag]; e = e < 0 ? 0 : (e > 7 ? 7 : e);
        src = Wd2 + (size_t)e * 65536;  oh = w4h + (size_t)ag * 65536;
        ol = w4l + (size_t)ag * 65536;  n4 = 16384; break;
    default:
        src = inputs + (size_t)ag * 524288; oh = inq + (size_t)ag * 524288;
        ol = nullptr; n4 = 131072; break;
    }
    if (seg == 4) {
        for (int i = blockIdx.x * 256 + threadIdx.x; i < n4; i += 32 * 256) {
            float4 v = ((const float4*)src)[i];
            ((uint2*)oh)[i] = make_uint2(pack2h(v.x, v.y), pack2h(v.z, v.w));
        }
    } else {
        for (int i = blockIdx.x * 256 + threadIdx.x; i < n4; i += 32 * 256) {
            float4 v = ((const float4*)src)[i];
            float h0 = h16r(v.x), h1 = h16r(v.y), h2 = h16r(v.z), h3 = h16r(v.w);
            ((uint2*)oh)[i] = make_uint2(pack2h(h0, h1), pack2h(h2, h3));
            ((uint2*)ol)[i] = make_uint2(pack2h(v.x - h0, v.y - h1),
                                         pack2h(v.z - h2, v.w - h3));
        }
    }
}

// ---------------- main GEMM ------------------------------------------------
// CTA tile 64m x 128n, 8 warps (2m x 4n, warp tile 32x32), BK=32, 3-stage
// cp.async. Stage: A 4KB | Bh 8KB | Bl 8KB = 20KB. 2 MMA passes (a*bh+a*bl).
// OMODE: 0 = fp32 out + bias, 1 = fp16 out + bias, 2 = raw fp32 partial.
// K = per-k-group depth, KROW = full A row stride (weight per-agent stride
// is KROW*N). blockIdx.x encodes (kgroup, n-tile): kg = bx/(N/128).
template <int K, int KROW, int N, bool RELU, int OMODE>
__global__ void __launch_bounds__(256, 3)
gemm_mma_kernel(const f16* __restrict__ A_,
                const f16* __restrict__ WH, const f16* __restrict__ WL,
                const float* __restrict__ Ball,
                float* __restrict__ Out,
                f16* __restrict__ Oq,
                const int* __restrict__ sel)
{
    extern __shared__ __align__(1024) char smem[];
    const uint32_t sb = smem_u32(smem);

    const int tid  = threadIdx.x;
    const int wid  = tid >> 5;
    const int lane = tid & 31;

    const int ag = blockIdx.z;
    int e = sel[ag]; e = e < 0 ? 0 : (e > 7 ? 7 : e);

    const int NX = N / 128;
    const int kg = blockIdx.x / NX;
    const int bn = (blockIdx.x % NX) * 128;
    const int bm = blockIdx.y * 64;

    const f16* Ap  = A_ + (size_t)ag * BATCH * KROW + (size_t)kg * K;
    const f16* Bh_ = WH + (size_t)ag * KROW * N + (size_t)kg * K * N;
    const f16* Bl_ = WL + (size_t)ag * KROW * N + (size_t)kg * K * N;
    const float* bp = Ball + (size_t)e * N;

    // smem: [0..512) bias fp32, [1024..) 3 x 20KB stage buffers
    if (OMODE != 2 && tid < 128) ((float*)smem)[tid] = bp[bn + tid];

    const int m0 = (wid >> 2) * 32;   // 2 m-groups
    const int n0 = (wid & 3) * 32;    // 4 n-groups

    const int lrow = lane & 15, lqh = lane >> 4;
    uint32_t aA[2];
#pragma unroll
    for (int mt = 0; mt < 2; mt++)
        aA[mt] = sb + 1024 + swa(m0 + mt * 16 + lrow, lqh);
    const int kr = (lane & 7) + ((lane >> 3) & 1) * 8;
    uint32_t bB[2];
#pragma unroll
    for (int g = 0; g < 2; g++) {
        int nch = ((n0 + g * 16) >> 3) + (lane >> 4);
        bB[g] = sb + 1024 + 4096 + kr * 256 + ((uint32_t)(nch ^ (kr & 7)) << 4);
    }

    float acc[2][4][4];
#pragma unroll
    for (int mt = 0; mt < 2; mt++)
#pragma unroll
        for (int nt = 0; nt < 4; nt++)
#pragma unroll
            for (int j = 0; j < 4; j++) acc[mt][nt][j] = 0.0f;

    const int NC = K / 32;

    auto ISSUE = [&](int c) {
        const int k0 = c * 32;
        const uint32_t s = sb + 1024 + (uint32_t)(c % 3) * 20480u;
        // A: 64 rows x 4 chunks(16B) = 256 chunks; 1/thread (single fp16)
        {
            int r = tid >> 2, cq = tid & 3;
            size_t go = (size_t)(bm + r) * KROW + k0 + cq * 8;
            cp16(s + swa(r, cq), Ap + go);
        }
        // B: 32 k-rows x 16 chunks(16B) = 512; 2/thread for h and l
#pragma unroll
        for (int i = 0; i < 2; i++) {
            int fid = i * 256 + tid;
            int r = fid >> 4, cq = fid & 15;
            size_t go = (size_t)(k0 + r) * N + bn + cq * 8;
            uint32_t ad = (uint32_t)(r * 256 + ((cq ^ (r & 7)) << 4));
            cp16(s + 4096 + ad,  Bh_ + go);
            cp16(s + 12288 + ad, Bl_ + go);
        }
        CP_COMMIT();
    };

    ISSUE(0);
    ISSUE(1);

    for (int c = 0; c < NC; c++) {
        if (c + 1 < NC) cp_wait<1>(); else cp_wait<0>();
        __syncthreads();
        if (c + 2 < NC) ISSUE(c + 2);

        const uint32_t stg = (uint32_t)(c % 3) * 20480u;
#pragma unroll
        for (int ks = 0; ks < 2; ks++) {
            uint32_t ah[2][4];
#pragma unroll
            for (int mt = 0; mt < 2; mt++)
                ldsm4(ah[mt], (aA[mt] + stg) ^ ((uint32_t)ks << 5));
#pragma unroll
            for (int g = 0; g < 2; g++) {
                uint32_t bh[4], bl[4];
                uint32_t bd = bB[g] + stg + (uint32_t)ks * 4096u;
                ldsm4t(bh, bd);
                ldsm4t(bl, bd + 8192);
#pragma unroll
                for (int mt = 0; mt < 2; mt++) {
                    const int nt = g * 2;
                    mma_f16(acc[mt][nt],     ah[mt], bh[0], bh[1]);
                    mma_f16(acc[mt][nt + 1], ah[mt], bh[2], bh[3]);
                    mma_f16(acc[mt][nt],     ah[mt], bl[0], bl[1]);
                    mma_f16(acc[mt][nt + 1], ah[mt], bl[2], bl[3]);
                }
            }
        }
    }

    // ---- epilogue ----
    const float* bias = (const float*)smem;
    float* Cp  = (OMODE == 0) ? (Out + (size_t)ag * BATCH * N) : nullptr;
    float* Pp  = (OMODE == 2) ? (Out + ((size_t)kg * NUM_AGENTS + ag) * BATCH * N) : nullptr;
    f16*   OqP = (OMODE == 1) ? (Oq + (size_t)ag * BATCH * N) : nullptr;

#pragma unroll
    for (int mt = 0; mt < 2; mt++) {
        const int mrow = bm + m0 + mt * 16 + (lane >> 2);
#pragma unroll
        for (int nt = 0; nt < 4; nt++) {
            const int nc = n0 + nt * 8 + 2 * (lane & 3);
            float o0 = acc[mt][nt][0], o1 = acc[mt][nt][1];
            float o2 = acc[mt][nt][2], o3 = acc[mt][nt][3];
            if (OMODE != 2) {
                const float b0 = bias[nc], b1 = bias[nc + 1];
                o0 += b0; o1 += b1; o2 += b0; o3 += b1;
            }
            if (RELU) {
                o0 = fmaxf(o0, 0.f); o1 = fmaxf(o1, 0.f);
                o2 = fmaxf(o2, 0.f); o3 = fmaxf(o3, 0.f);
            }
            const size_t i0 = (size_t)mrow * N + bn + nc;
            const size_t i1 = (size_t)(mrow + 8) * N + bn + nc;
            if (OMODE == 1) {
                *(uint32_t*)(OqP + i0) = pack2h(o0, o1);
                *(uint32_t*)(OqP + i1) = pack2h(o2, o3);
            } else if (OMODE == 0) {
                *(float2*)(Cp + i0) = make_float2(o0, o1);
                *(float2*)(Cp + i1) = make_float2(o2, o3);
            } else {
                *(float2*)(Pp + i0) = make_float2(o0, o1);
                *(float2*)(Pp + i1) = make_float2(o2, o3);
            }
        }
    }
}

// ---------------- split-K reduce: out = p0 + p1 + bias ---------------------
__global__ void __launch_bounds__(256)
reduce4_kernel(const float* __restrict__ P, const float* __restrict__ Ball,
               const int* __restrict__ sel_d, float* __restrict__ out)
{
    const int i = blockIdx.x * 256 + threadIdx.x;          // float4 index
    const float4 a = ((const float4*)P)[i];
    const float4 b = ((const float4*)P)[i + 524288];
    const int e4 = i * 4;
    const int ag = e4 >> 18;                               // / (2048*128)
    int e = sel_d[ag]; e = e < 0 ? 0 : (e > 7 ? 7 : e);
    const float4 bb = *(const float4*)(Ball + e * 128 + (e4 & 127));
    ((float4*)out)[i] = make_float4(a.x + b.x + bb.x, a.y + b.y + bb.y,
                                    a.z + b.z + bb.z, a.w + b.w + bb.w);
}

// ---------------------------------------------------------------------------
extern "C" void kernel_launch(void* const* d_in, const int* in_sizes, int n_in,
                              void* d_out, int out_size)
{
    const float* inputs = (const float*)d_in[0];
    const int*   sel_s  = (const int*)d_in[1];
    const int*   sel_d  = (const int*)d_in[2];
    const float* Ws1 = (const float*)d_in[3];
    const float* bs1 = (const float*)d_in[4];
    const float* Ws2 = (const float*)d_in[5];
    const float* bs2 = (const float*)d_in[6];
    const float* Wd1 = (const float*)d_in[7];
    const float* bd1 = (const float*)d_in[8];
    const float* Wd2 = (const float*)d_in[9];
    const float* bd2 = (const float*)d_in[10];
    float* out = (float*)d_out;

    void* p;
    f16 *inq, *y1, *y2, *y3;
    float* p4;
    cudaGetSymbolAddress(&p, g_inq); inq = (f16*)p;
    cudaGetSymbolAddress(&p, g_y1);  y1  = (f16*)p;
    cudaGetSymbolAddress(&p, g_y2);  y2  = (f16*)p;
    cudaGetSymbolAddress(&p, g_y3);  y3  = (f16*)p;
    cudaGetSymbolAddress(&p, g_p4);  p4  = (float*)p;
    f16 *w1h, *w1l, *w2h, *w2l, *w3h, *w3l, *w4h, *w4l;
    cudaGetSymbolAddress(&p, g_w1h); w1h = (f16*)p;
    cudaGetSymbolAddress(&p, g_w1l); w1l = (f16*)p;
    cudaGetSymbolAddress(&p, g_w2h); w2h = (f16*)p;
    cudaGetSymbolAddress(&p, g_w2l); w2l = (f16*)p;
    cudaGetSymbolAddress(&p, g_w3h); w3h = (f16*)p;
    cudaGetSymbolAddress(&p, g_w3l); w3l = (f16*)p;
    cudaGetSymbolAddress(&p, g_w4h); w4h = (f16*)p;
    cudaGetSymbolAddress(&p, g_w4l); w4l = (f16*)p;

    const int SMEM_BYTES = 1024 + 3 * 20480;   // 62464
    // Three distinct instantiations (L1 and L3 share one); each needs opt-in.
    cudaFuncSetAttribute(gemm_mma_kernel<256, 256, 512, true,  1>,
                         cudaFuncAttributeMaxDynamicSharedMemorySize, SMEM_BYTES);
    cudaFuncSetAttribute(gemm_mma_kernel<512, 512, 256, true,  1>,
                         cudaFuncAttributeMaxDynamicSharedMemorySize, SMEM_BYTES);
    cudaFuncSetAttribute(gemm_mma_kernel<256, 512, 128, false, 2>,
                         cudaFuncAttributeMaxDynamicSharedMemorySize, SMEM_BYTES);

    prep_kernel<<<dim3(32, 5, 8), 256>>>(Ws1, Ws2, Wd1, Wd2, inputs, sel_s, sel_d,
                                         w1h, w1l, w2h, w2l, w3h, w3l, w4h, w4l,
                                         inq);

    dim3 blk(256);
    gemm_mma_kernel<256, 256, 512, true,  1><<<dim3(4, 32, 8), blk, SMEM_BYTES>>>(
        inq, w1h, w1l, bs1, nullptr, y1, sel_s);
    gemm_mma_kernel<512, 512, 256, true,  1><<<dim3(2, 32, 8), blk, SMEM_BYTES>>>(
        y1, w2h, w2l, bs2, nullptr, y2, sel_s);
    gemm_mma_kernel<256, 256, 512, true,  1><<<dim3(4, 32, 8), blk, SMEM_BYTES>>>(
        y2, w3h, w3l, bd1, nullptr, y3, sel_d);
    // L4: split-K x2 -> raw partials, then deterministic reduce (+bias)
    gemm_mma_kernel<256, 512, 128, false, 2><<<dim3(2, 32, 8), blk, SMEM_BYTES>>>(
        y3, w4h, w4l, bd2, p4, nullptr, sel_d);
    reduce4_kernel<<<2048, 256>>>(p4, bd2, sel_d, out);
}

// round 14
// speedup vs baseline: 2.1224x; 1.3664x over previous
#include <cuda_runtime.h>
#include <cuda_fp16.h>
#include <cstdint>

// ---------------------------------------------------------------------------
// MADPSNet via mma.sync fp16 single-pass GEMMs, v8.
//   Roofline model (validated R9-R13): dur scales linearly with MMA pass
//   count at the fixed mma.sync HMMA rate (~53% tensor). v8 drops the
//   weight lo-term: plain fp16 x fp16 with fp32 accumulate, 1 pass.
//   Error model (calibrated on R13: 4 activation roundings = 4.05e-4):
//   adding 4 weight roundings -> ~sqrt(2)*4.05e-4 ~ 5.7e-4 < 1e-3 gate.
//   Keeps R10 config: 64x128 CTA, 3 CTAs/SM, 3-stage cp.async, fused
//   prepass, split-K x2 L4 + deterministic reduce.
// ---------------------------------------------------------------------------

#define NUM_AGENTS 8
#define BATCH      2048
typedef __half f16;

// ---------------- scratch (__device__ globals) ----------------------------
__device__ f16 g_inq[NUM_AGENTS * BATCH * 256];     // fp16 input
__device__ f16 g_y1[NUM_AGENTS * BATCH * 512];      // fp16 activations
__device__ f16 g_y2[NUM_AGENTS * BATCH * 256];
__device__ f16 g_y3[NUM_AGENTS * BATCH * 512];
__device__ float g_p4[2 * NUM_AGENTS * BATCH * 128];   // L4 split-K partials

__device__ f16 g_w1[NUM_AGENTS * 256 * 512];
__device__ f16 g_w2[NUM_AGENTS * 512 * 256];
__device__ f16 g_w3[NUM_AGENTS * 256 * 512];
__device__ f16 g_w4[NUM_AGENTS * 512 * 128];

// ---------------- helpers --------------------------------------------------
__device__ __forceinline__ uint32_t smem_u32(const void* p) {
    uint32_t a;
    asm("{ .reg .u64 t; cvta.to.shared.u64 t, %1; cvt.u32.u64 %0, t; }" : "=r"(a) : "l"(p));
    return a;
}
__device__ __forceinline__ void ldsm4(uint32_t (&r)[4], uint32_t addr) {
    asm volatile("ldmatrix.sync.aligned.m8n8.x4.shared.b16 {%0,%1,%2,%3}, [%4];"
                 : "=r"(r[0]), "=r"(r[1]), "=r"(r[2]), "=r"(r[3]) : "r"(addr));
}
__device__ __forceinline__ void ldsm4t(uint32_t (&r)[4], uint32_t addr) {
    asm volatile("ldmatrix.sync.aligned.m8n8.x4.trans.shared.b16 {%0,%1,%2,%3}, [%4];"
                 : "=r"(r[0]), "=r"(r[1]), "=r"(r[2]), "=r"(r[3]) : "r"(addr));
}
__device__ __forceinline__ void mma_f16(float (&d)[4], const uint32_t (&a)[4],
                                        uint32_t b0, uint32_t b1) {
    asm volatile(
        "mma.sync.aligned.m16n8k16.row.col.f32.f16.f16.f32 "
        "{%0,%1,%2,%3}, {%4,%5,%6,%7}, {%8,%9}, {%0,%1,%2,%3};"
        : "+f"(d[0]), "+f"(d[1]), "+f"(d[2]), "+f"(d[3])
        : "r"(a[0]), "r"(a[1]), "r"(a[2]), "r"(a[3]), "r"(b0), "r"(b1));
}
__device__ __forceinline__ void cp16(uint32_t dst, const void* src) {
    asm volatile("cp.async.cg.shared.global [%0], [%1], 16;" :: "r"(dst), "l"(src));
}
template <int NW>
__device__ __forceinline__ void cp_wait() {
    asm volatile("cp.async.wait_group %0;" :: "n"(NW));
}
#define CP_COMMIT() asm volatile("cp.async.commit_group;" ::: "memory")

__device__ __forceinline__ uint32_t pack2h(float a, float b) {
    __half2 t = __floats2half2_rn(a, b);
    return *reinterpret_cast<uint32_t*>(&t);
}
// A-tile swizzle: rows x 32 fp16 (64B rows)
__device__ __forceinline__ uint32_t swa(int row, int c16) {
    return (uint32_t)(row * 64 + (((c16) ^ ((row >> 1) & 3)) << 4));
}

// ---------------- fused prepass: fp32 -> fp16 conversions ------------------
// seg 0..3: selected weight mats; seg 4: input.
__global__ void __launch_bounds__(256)
prep_kernel(const float* __restrict__ Ws1, const float* __restrict__ Ws2,
            const float* __restrict__ Wd1, const float* __restrict__ Wd2,
            const float* __restrict__ inputs,
            const int* __restrict__ sel_s, const int* __restrict__ sel_d,
            f16* __restrict__ w1, f16* __restrict__ w2,
            f16* __restrict__ w3, f16* __restrict__ w4,
            f16* __restrict__ inq)
{
    const int seg = blockIdx.y;
    const int ag  = blockIdx.z;
    const float* src;
    f16* oq;
    int n4;
    int e;
    switch (seg) {
    case 0:
        e = sel_s[ag]; e = e < 0 ? 0 : (e > 7 ? 7 : e);
        src = Ws1 + (size_t)e * 131072; oq = w1 + (size_t)ag * 131072;
        n4 = 32768; break;
    case 1:
        e = sel_s[ag]; e = e < 0 ? 0 : (e > 7 ? 7 : e);
        src = Ws2 + (size_t)e * 131072; oq = w2 + (size_t)ag * 131072;
        n4 = 32768; break;
    case 2:
        e = sel_d[ag]; e = e < 0 ? 0 : (e > 7 ? 7 : e);
        src = Wd1 + (size_t)e * 131072; oq = w3 + (size_t)ag * 131072;
        n4 = 32768; break;
    case 3:
        e = sel_d[ag]; e = e < 0 ? 0 : (e > 7 ? 7 : e);
        src = Wd2 + (size_t)e * 65536;  oq = w4 + (size_t)ag * 65536;
        n4 = 16384; break;
    default:
        src = inputs + (size_t)ag * 524288; oq = inq + (size_t)ag * 524288;
        n4 = 131072; break;
    }
    for (int i = blockIdx.x * 256 + threadIdx.x; i < n4; i += 32 * 256) {
        float4 v = ((const float4*)src)[i];
        ((uint2*)oq)[i] = make_uint2(pack2h(v.x, v.y), pack2h(v.z, v.w));
    }
}

// ---------------- main GEMM ------------------------------------------------
// CTA tile 64m x 128n, 8 warps (2m x 4n, warp tile 32x32), BK=32, 3-stage
// cp.async. Stage: A 4KB | B 8KB = 12KB. Single fp16 MMA pass.
// OMODE: 0 = fp32 out + bias, 1 = fp16 out + bias, 2 = raw fp32 partial.
// K = per-k-group depth, KROW = full A row stride (weight per-agent stride
// is KROW*N). blockIdx.x encodes (kgroup, n-tile): kg = bx/(N/128).
template <int K, int KROW, int N, bool RELU, int OMODE>
__global__ void __launch_bounds__(256, 3)
gemm_mma_kernel(const f16* __restrict__ A_,
                const f16* __restrict__ W_,
                const float* __restrict__ Ball,
                float* __restrict__ Out,
                f16* __restrict__ Oq,
                const int* __restrict__ sel)
{
    extern __shared__ __align__(1024) char smem[];
    const uint32_t sb = smem_u32(smem);

    const int tid  = threadIdx.x;
    const int wid  = tid >> 5;
    const int lane = tid & 31;

    const int ag = blockIdx.z;
    int e = sel[ag]; e = e < 0 ? 0 : (e > 7 ? 7 : e);

    const int NX = N / 128;
    const int kg = blockIdx.x / NX;
    const int bn = (blockIdx.x % NX) * 128;
    const int bm = blockIdx.y * 64;

    const f16* Ap = A_ + (size_t)ag * BATCH * KROW + (size_t)kg * K;
    const f16* Bp = W_ + (size_t)ag * KROW * N + (size_t)kg * K * N;
    const float* bp = Ball + (size_t)e * N;

    // smem: [0..512) bias fp32, [1024..) 3 x 12KB stage buffers
    if (OMODE != 2 && tid < 128) ((float*)smem)[tid] = bp[bn + tid];

    const int m0 = (wid >> 2) * 32;   // 2 m-groups
    const int n0 = (wid & 3) * 32;    // 4 n-groups

    const int lrow = lane & 15, lqh = lane >> 4;
    uint32_t aA[2];
#pragma unroll
    for (int mt = 0; mt < 2; mt++)
        aA[mt] = sb + 1024 + swa(m0 + mt * 16 + lrow, lqh);
    const int kr = (lane & 7) + ((lane >> 3) & 1) * 8;
    uint32_t bB[2];
#pragma unroll
    for (int g = 0; g < 2; g++) {
        int nch = ((n0 + g * 16) >> 3) + (lane >> 4);
        bB[g] = sb + 1024 + 4096 + kr * 256 + ((uint32_t)(nch ^ (kr & 7)) << 4);
    }

    float acc[2][4][4];
#pragma unroll
    for (int mt = 0; mt < 2; mt++)
#pragma unroll
        for (int nt = 0; nt < 4; nt++)
#pragma unroll
            for (int j = 0; j < 4; j++) acc[mt][nt][j] = 0.0f;

    const int NC = K / 32;

    auto ISSUE = [&](int c) {
        const int k0 = c * 32;
        const uint32_t s = sb + 1024 + (uint32_t)(c % 3) * 12288u;
        // A: 64 rows x 4 chunks(16B) = 256 chunks; 1/thread
        {
            int r = tid >> 2, cq = tid & 3;
            size_t go = (size_t)(bm + r) * KROW + k0 + cq * 8;
            cp16(s + swa(r, cq), Ap + go);
        }
        // B: 32 k-rows x 16 chunks(16B) = 512; 2/thread
#pragma unroll
        for (int i = 0; i < 2; i++) {
            int fid = i * 256 + tid;
            int r = fid >> 4, cq = fid & 15;
            size_t go = (size_t)(k0 + r) * N + bn + cq * 8;
            uint32_t ad = (uint32_t)(r * 256 + ((cq ^ (r & 7)) << 4));
            cp16(s + 4096 + ad, Bp + go);
        }
        CP_COMMIT();
    };

    ISSUE(0);
    ISSUE(1);

    for (int c = 0; c < NC; c++) {
        if (c + 1 < NC) cp_wait<1>(); else cp_wait<0>();
        __syncthreads();
        if (c + 2 < NC) ISSUE(c + 2);

        const uint32_t stg = (uint32_t)(c % 3) * 12288u;
#pragma unroll
        for (int ks = 0; ks < 2; ks++) {
            uint32_t ah[2][4];
#pragma unroll
            for (int mt = 0; mt < 2; mt++)
                ldsm4(ah[mt], (aA[mt] + stg) ^ ((uint32_t)ks << 5));
#pragma unroll
            for (int g = 0; g < 2; g++) {
                uint32_t b[4];
                ldsm4t(b, bB[g] + stg + (uint32_t)ks * 4096u);
#pragma unroll
                for (int mt = 0; mt < 2; mt++) {
                    const int nt = g * 2;
                    mma_f16(acc[mt][nt],     ah[mt], b[0], b[1]);
                    mma_f16(acc[mt][nt + 1], ah[mt], b[2], b[3]);
                }
            }
        }
    }

    // ---- epilogue ----
    const float* bias = (const float*)smem;
    float* Cp  = (OMODE == 0) ? (Out + (size_t)ag * BATCH * N) : nullptr;
    float* Pp  = (OMODE == 2) ? (Out + ((size_t)kg * NUM_AGENTS + ag) * BATCH * N) : nullptr;
    f16*   OqP = (OMODE == 1) ? (Oq + (size_t)ag * BATCH * N) : nullptr;

#pragma unroll
    for (int mt = 0; mt < 2; mt++) {
        const int mrow = bm + m0 + mt * 16 + (lane >> 2);
#pragma unroll
        for (int nt = 0; nt < 4; nt++) {
            const int nc = n0 + nt * 8 + 2 * (lane & 3);
            float o0 = acc[mt][nt][0], o1 = acc[mt][nt][1];
            float o2 = acc[mt][nt][2], o3 = acc[mt][nt][3];
            if (OMODE != 2) {
                const float b0 = bias[nc], b1 = bias[nc + 1];
                o0 += b0; o1 += b1; o2 += b0; o3 += b1;
            }
            if (RELU) {
                o0 = fmaxf(o0, 0.f); o1 = fmaxf(o1, 0.f);
                o2 = fmaxf(o2, 0.f); o3 = fmaxf(o3, 0.f);
            }
            const size_t i0 = (size_t)mrow * N + bn + nc;
            const size_t i1 = (size_t)(mrow + 8) * N + bn + nc;
            if (OMODE == 1) {
                *(uint32_t*)(OqP + i0) = pack2h(o0, o1);
                *(uint32_t*)(OqP + i1) = pack2h(o2, o3);
            } else if (OMODE == 0) {
                *(float2*)(Cp + i0) = make_float2(o0, o1);
                *(float2*)(Cp + i1) = make_float2(o2, o3);
            } else {
                *(float2*)(Pp + i0) = make_float2(o0, o1);
                *(float2*)(Pp + i1) = make_float2(o2, o3);
            }
        }
    }
}

// ---------------- split-K reduce: out = p0 + p1 + bias ---------------------
__global__ void __launch_bounds__(256)
reduce4_kernel(const float* __restrict__ P, const float* __restrict__ Ball,
               const int* __restrict__ sel_d, float* __restrict__ out)
{
    const int i = blockIdx.x * 256 + threadIdx.x;          // float4 index
    const float4 a = ((const float4*)P)[i];
    const float4 b = ((const float4*)P)[i + 524288];
    const int e4 = i * 4;
    const int ag = e4 >> 18;                               // / (2048*128)
    int e = sel_d[ag]; e = e < 0 ? 0 : (e > 7 ? 7 : e);
    const float4 bb = *(const float4*)(Ball + e * 128 + (e4 & 127));
    ((float4*)out)[i] = make_float4(a.x + b.x + bb.x, a.y + b.y + bb.y,
                                    a.z + b.z + bb.z, a.w + b.w + bb.w);
}

// ---------------------------------------------------------------------------
extern "C" void kernel_launch(void* const* d_in, const int* in_sizes, int n_in,
                              void* d_out, int out_size)
{
    const float* inputs = (const float*)d_in[0];
    const int*   sel_s  = (const int*)d_in[1];
    const int*   sel_d  = (const int*)d_in[2];
    const float* Ws1 = (const float*)d_in[3];
    const float* bs1 = (const float*)d_in[4];
    const float* Ws2 = (const float*)d_in[5];
    const float* bs2 = (const float*)d_in[6];
    const float* Wd1 = (const float*)d_in[7];
    const float* bd1 = (const float*)d_in[8];
    const float* Wd2 = (const float*)d_in[9];
    const float* bd2 = (const float*)d_in[10];
    float* out = (float*)d_out;

    void* p;
    f16 *inq, *y1, *y2, *y3, *w1, *w2, *w3, *w4;
    float* p4;
    cudaGetSymbolAddress(&p, g_inq); inq = (f16*)p;
    cudaGetSymbolAddress(&p, g_y1);  y1  = (f16*)p;
    cudaGetSymbolAddress(&p, g_y2);  y2  = (f16*)p;
    cudaGetSymbolAddress(&p, g_y3);  y3  = (f16*)p;
    cudaGetSymbolAddress(&p, g_p4);  p4  = (float*)p;
    cudaGetSymbolAddress(&p, g_w1);  w1  = (f16*)p;
    cudaGetSymbolAddress(&p, g_w2);  w2  = (f16*)p;
    cudaGetSymbolAddress(&p, g_w3);  w3  = (f16*)p;
    cudaGetSymbolAddress(&p, g_w4);  w4  = (f16*)p;

    const int SMEM_BYTES = 1024 + 3 * 12288;   // 37888 (fits default cap; opt-in harmless)
    cudaFuncSetAttribute(gemm_mma_kernel<256, 256, 512, true,  1>,
                         cudaFuncAttributeMaxDynamicSharedMemorySize, SMEM_BYTES);
    cudaFuncSetAttribute(gemm_mma_kernel<512, 512, 256, true,  1>,
                         cudaFuncAttributeMaxDynamicSharedMemorySize, SMEM_BYTES);
    cudaFuncSetAttribute(gemm_mma_kernel<256, 512, 128, false, 2>,
                         cudaFuncAttributeMaxDynamicSharedMemorySize, SMEM_BYTES);

    prep_kernel<<<dim3(32, 5, 8), 256>>>(Ws1, Ws2, Wd1, Wd2, inputs, sel_s, sel_d,
                                         w1, w2, w3, w4, inq);

    dim3 blk(256);
    gemm_mma_kernel<256, 256, 512, true,  1><<<dim3(4, 32, 8), blk, SMEM_BYTES>>>(
        inq, w1, bs1, nullptr, y1, sel_s);
    gemm_mma_kernel<512, 512, 256, true,  1><<<dim3(2, 32, 8), blk, SMEM_BYTES>>>(
        y1, w2, bs2, nullptr, y2, sel_s);
    gemm_mma_kernel<256, 256, 512, true,  1><<<dim3(4, 32, 8), blk, SMEM_BYTES>>>(
        y2, w3, bd1, nullptr, y3, sel_d);
    // L4: split-K x2 -> raw partials, then deterministic reduce (+bias)
    gemm_mma_kernel<256, 512, 128, false, 2><<<dim3(2, 32, 8), blk, SMEM_BYTES>>>(
        y3, w4, bd2, p4, nullptr, sel_d);
    reduce4_kernel<<<2048, 256>>>(p4, bd2, sel_d, out);
}

// round 15
// speedup vs baseline: 2.1943x; 1.0339x over previous
#include <cuda_runtime.h>
#include <cuda_fp16.h>
#include <cstdint>

// ---------------------------------------------------------------------------
// MADPSNet via mma.sync fp16 single-pass GEMMs, v9.
//   v9: CTA tile 128x128 (8 warps, warp tile 32m x 64n -> 192B ldsm/MMA,
//   was 256B) + BK=64 (half the barrier epochs). 2 CTAs/SM, 3-stage
//   cp.async (32KB/stage). L1/L3: 1.73 waves; L2/L4: single wave.
//   Numerics unchanged from v8: fp16 x fp16 -> fp32 acc, single pass
//   (rel_err 5.75e-4, calibrated).
// ---------------------------------------------------------------------------

#define NUM_AGENTS 8
#define BATCH      2048
typedef __half f16;

// ---------------- scratch (__device__ globals) ----------------------------
__device__ f16 g_inq[NUM_AGENTS * BATCH * 256];     // fp16 input
__device__ f16 g_y1[NUM_AGENTS * BATCH * 512];      // fp16 activations
__device__ f16 g_y2[NUM_AGENTS * BATCH * 256];
__device__ f16 g_y3[NUM_AGENTS * BATCH * 512];
__device__ float g_p4[2 * NUM_AGENTS * BATCH * 128];   // L4 split-K partials

__device__ f16 g_w1[NUM_AGENTS * 256 * 512];
__device__ f16 g_w2[NUM_AGENTS * 512 * 256];
__device__ f16 g_w3[NUM_AGENTS * 256 * 512];
__device__ f16 g_w4[NUM_AGENTS * 512 * 128];

// ---------------- helpers --------------------------------------------------
__device__ __forceinline__ uint32_t smem_u32(const void* p) {
    uint32_t a;
    asm("{ .reg .u64 t; cvta.to.shared.u64 t, %1; cvt.u32.u64 %0, t; }" : "=r"(a) : "l"(p));
    return a;
}
__device__ __forceinline__ void ldsm4(uint32_t (&r)[4], uint32_t addr) {
    asm volatile("ldmatrix.sync.aligned.m8n8.x4.shared.b16 {%0,%1,%2,%3}, [%4];"
                 : "=r"(r[0]), "=r"(r[1]), "=r"(r[2]), "=r"(r[3]) : "r"(addr));
}
__device__ __forceinline__ void ldsm4t(uint32_t (&r)[4], uint32_t addr) {
    asm volatile("ldmatrix.sync.aligned.m8n8.x4.trans.shared.b16 {%0,%1,%2,%3}, [%4];"
                 : "=r"(r[0]), "=r"(r[1]), "=r"(r[2]), "=r"(r[3]) : "r"(addr));
}
__device__ __forceinline__ void mma_f16(float (&d)[4], const uint32_t (&a)[4],
                                        uint32_t b0, uint32_t b1) {
    asm volatile(
        "mma.sync.aligned.m16n8k16.row.col.f32.f16.f16.f32 "
        "{%0,%1,%2,%3}, {%4,%5,%6,%7}, {%8,%9}, {%0,%1,%2,%3};"
        : "+f"(d[0]), "+f"(d[1]), "+f"(d[2]), "+f"(d[3])
        : "r"(a[0]), "r"(a[1]), "r"(a[2]), "r"(a[3]), "r"(b0), "r"(b1));
}
__device__ __forceinline__ void cp16(uint32_t dst, const void* src) {
    asm volatile("cp.async.cg.shared.global [%0], [%1], 16;" :: "r"(dst), "l"(src));
}
template <int NW>
__device__ __forceinline__ void cp_wait() {
    asm volatile("cp.async.wait_group %0;" :: "n"(NW));
}
#define CP_COMMIT() asm volatile("cp.async.commit_group;" ::: "memory")

__device__ __forceinline__ uint32_t pack2h(float a, float b) {
    __half2 t = __floats2half2_rn(a, b);
    return *reinterpret_cast<uint32_t*>(&t);
}

// ---------------- fused prepass: fp32 -> fp16 conversions ------------------
__global__ void __launch_bounds__(256)
prep_kernel(const float* __restrict__ Ws1, const float* __restrict__ Ws2,
            const float* __restrict__ Wd1, const float* __restrict__ Wd2,
            const float* __restrict__ inputs,
            const int* __restrict__ sel_s, const int* __restrict__ sel_d,
            f16* __restrict__ w1, f16* __restrict__ w2,
            f16* __restrict__ w3, f16* __restrict__ w4,
            f16* __restrict__ inq)
{
    const int seg = blockIdx.y;
    const int ag  = blockIdx.z;
    const float* src;
    f16* oq;
    int n4;
    int e;
    switch (seg) {
    case 0:
        e = sel_s[ag]; e = e < 0 ? 0 : (e > 7 ? 7 : e);
        src = Ws1 + (size_t)e * 131072; oq = w1 + (size_t)ag * 131072;
        n4 = 32768; break;
    case 1:
        e = sel_s[ag]; e = e < 0 ? 0 : (e > 7 ? 7 : e);
        src = Ws2 + (size_t)e * 131072; oq = w2 + (size_t)ag * 131072;
        n4 = 32768; break;
    case 2:
        e = sel_d[ag]; e = e < 0 ? 0 : (e > 7 ? 7 : e);
        src = Wd1 + (size_t)e * 131072; oq = w3 + (size_t)ag * 131072;
        n4 = 32768; break;
    case 3:
        e = sel_d[ag]; e = e < 0 ? 0 : (e > 7 ? 7 : e);
        src = Wd2 + (size_t)e * 65536;  oq = w4 + (size_t)ag * 65536;
        n4 = 16384; break;
    default:
        src = inputs + (size_t)ag * 524288; oq = inq + (size_t)ag * 524288;
        n4 = 131072; break;
    }
    for (int i = blockIdx.x * 256 + threadIdx.x; i < n4; i += 32 * 256) {
        float4 v = ((const float4*)src)[i];
        ((uint2*)oq)[i] = make_uint2(pack2h(v.x, v.y), pack2h(v.z, v.w));
    }
}

// ---------------- main GEMM ------------------------------------------------
// CTA tile 128m x 128n, 8 warps (4m x 2n, warp tile 32m x 64n), BK=64,
// 3-stage cp.async. Stage: A 16KB (128 rows x 128B swz) | B 16KB (64 rows
// x 256B swz) = 32KB. Single fp16 MMA pass.
// OMODE: 0 = fp32 out + bias, 1 = fp16 out + bias, 2 = raw fp32 partial.
// K = per-k-group depth, KROW = full A row stride (weight per-agent stride
// is KROW*N). blockIdx.x encodes (kgroup, n-tile): kg = bx/(N/128).
template <int K, int KROW, int N, bool RELU, int OMODE>
__global__ void __launch_bounds__(256, 2)
gemm_mma_kernel(const f16* __restrict__ A_,
                const f16* __restrict__ W_,
                const float* __restrict__ Ball,
                float* __restrict__ Out,
                f16* __restrict__ Oq,
                const int* __restrict__ sel)
{
    extern __shared__ __align__(1024) char smem[];
    const uint32_t sb = smem_u32(smem);

    const int tid  = threadIdx.x;
    const int wid  = tid >> 5;
    const int lane = tid & 31;

    const int ag = blockIdx.z;
    int e = sel[ag]; e = e < 0 ? 0 : (e > 7 ? 7 : e);

    const int NX = N / 128;
    const int kg = blockIdx.x / NX;
    const int bn = (blockIdx.x % NX) * 128;
    const int bm = blockIdx.y * 128;

    const f16* Ap = A_ + (size_t)ag * BATCH * KROW + (size_t)kg * K;
    const f16* Bp = W_ + (size_t)ag * KROW * N + (size_t)kg * K * N;
    const float* bp = Ball + (size_t)e * N;

    // smem: [0..512) bias fp32, [1024..) 3 x 32KB stage buffers
    if (OMODE != 2 && tid < 128) ((float*)smem)[tid] = bp[bn + tid];

    const int m0 = (wid >> 1) * 32;   // 4 m-groups
    const int n0 = (wid & 1) * 64;    // 2 n-groups

    // A ldsm bases: row r = m0 + mt*16 + (lane&15); chunk = ks*2 + (lane>>4)
    // swizzled ((chunk ^ (r&7))<<4); ks applied by XOR (ks<<5) (disjoint bits).
    const int lrow = lane & 15, lqh = lane >> 4;
    uint32_t aA[2];
#pragma unroll
    for (int mt = 0; mt < 2; mt++) {
        int r = m0 + mt * 16 + lrow;
        aA[mt] = sb + 1024 + (uint32_t)(r * 128 + (((lqh) ^ (r & 7)) << 4));
    }
    // B (trans) bases: k-row kr, 16B n-chunk nch, +ks*4096 per ks
    const int kr = (lane & 7) + ((lane >> 3) & 1) * 8;
    uint32_t bB[4];
#pragma unroll
    for (int g = 0; g < 4; g++) {
        int nch = ((n0 + g * 16) >> 3) + (lane >> 4);
        bB[g] = sb + 1024 + 16384 + (uint32_t)(kr * 256 + ((nch ^ (kr & 7)) << 4));
    }

    float acc[2][8][4];
#pragma unroll
    for (int mt = 0; mt < 2; mt++)
#pragma unroll
        for (int nt = 0; nt < 8; nt++)
#pragma unroll
            for (int j = 0; j < 4; j++) acc[mt][nt][j] = 0.0f;

    const int NC = K / 64;

    auto ISSUE = [&](int c) {
        const int k0 = c * 64;
        const uint32_t s = sb + 1024 + (uint32_t)(c % 3) * 32768u;
        // A: 128 rows x 8 chunks(16B) = 1024; 4/thread
#pragma unroll
        for (int i = 0; i < 4; i++) {
            int fid = i * 256 + tid;
            int r = fid >> 3, cq = fid & 7;
            size_t go = (size_t)(bm + r) * KROW + k0 + cq * 8;
            cp16(s + (uint32_t)(r * 128 + ((cq ^ (r & 7)) << 4)), Ap + go);
        }
        // B: 64 k-rows x 16 chunks(16B) = 1024; 4/thread
#pragma unroll
        for (int i = 0; i < 4; i++) {
            int fid = i * 256 + tid;
            int r = fid >> 4, cq = fid & 15;
            size_t go = (size_t)(k0 + r) * N + bn + cq * 8;
            cp16(s + 16384 + (uint32_t)(r * 256 + ((cq ^ (r & 7)) << 4)), Bp + go);
        }
        CP_COMMIT();
    };

    ISSUE(0);
    ISSUE(1);

    for (int c = 0; c < NC; c++) {
        if (c + 1 < NC) cp_wait<1>(); else cp_wait<0>();
        __syncthreads();
        if (c + 2 < NC) ISSUE(c + 2);

        const uint32_t stg = (uint32_t)(c % 3) * 32768u;
#pragma unroll
        for (int ks = 0; ks < 4; ks++) {
            uint32_t ah[2][4];
#pragma unroll
            for (int mt = 0; mt < 2; mt++)
                ldsm4(ah[mt], (aA[mt] + stg) ^ ((uint32_t)ks << 5));
#pragma unroll
            for (int g = 0; g < 4; g++) {
                uint32_t b[4];
                ldsm4t(b, bB[g] + stg + (uint32_t)ks * 4096u);
#pragma unroll
                for (int mt = 0; mt < 2; mt++) {
                    const int nt = g * 2;
                    mma_f16(acc[mt][nt],     ah[mt], b[0], b[1]);
                    mma_f16(acc[mt][nt + 1], ah[mt], b[2], b[3]);
                }
            }
        }
    }

    // ---- epilogue: warp covers rows m0..m0+31, cols n0..n0+63 ----
    const float* bias = (const float*)smem;
    float* Cp  = (OMODE == 0) ? (Out + (size_t)ag * BATCH * N) : nullptr;
    float* Pp  = (OMODE == 2) ? (Out + ((size_t)kg * NUM_AGENTS + ag) * BATCH * N) : nullptr;
    f16*   OqP = (OMODE == 1) ? (Oq + (size_t)ag * BATCH * N) : nullptr;

#pragma unroll
    for (int mt = 0; mt < 2; mt++) {
        const int mrow = bm + m0 + mt * 16 + (lane >> 2);
#pragma unroll
        for (int nt = 0; nt < 8; nt++) {
            const int nc = n0 + nt * 8 + 2 * (lane & 3);
            float o0 = acc[mt][nt][0], o1 = acc[mt][nt][1];
            float o2 = acc[mt][nt][2], o3 = acc[mt][nt][3];
            if (OMODE != 2) {
                const float b0 = bias[nc], b1 = bias[nc + 1];
                o0 += b0; o1 += b1; o2 += b0; o3 += b1;
            }
            if (RELU) {
                o0 = fmaxf(o0, 0.f); o1 = fmaxf(o1, 0.f);
                o2 = fmaxf(o2, 0.f); o3 = fmaxf(o3, 0.f);
            }
            const size_t i0 = (size_t)mrow * N + bn + nc;
            const size_t i1 = (size_t)(mrow + 8) * N + bn + nc;
            if (OMODE == 1) {
                *(uint32_t*)(OqP + i0) = pack2h(o0, o1);
                *(uint32_t*)(OqP + i1) = pack2h(o2, o3);
            } else if (OMODE == 0) {
                *(float2*)(Cp + i0) = make_float2(o0, o1);
                *(float2*)(Cp + i1) = make_float2(o2, o3);
            } else {
                *(float2*)(Pp + i0) = make_float2(o0, o1);
                *(float2*)(Pp + i1) = make_float2(o2, o3);
            }
        }
    }
}

// ---------------- split-K reduce: out = p0 + p1 + bias ---------------------
__global__ void __launch_bounds__(256)
reduce4_kernel(const float* __restrict__ P, const float* __restrict__ Ball,
               const int* __restrict__ sel_d, float* __restrict__ out)
{
    const int i = blockIdx.x * 256 + threadIdx.x;          // float4 index
    const float4 a = ((const float4*)P)[i];
    const float4 b = ((const float4*)P)[i + 524288];
    const int e4 = i * 4;
    const int ag = e4 >> 18;                               // / (2048*128)
    int e = sel_d[ag]; e = e < 0 ? 0 : (e > 7 ? 7 : e);
    const float4 bb = *(const float4*)(Ball + e * 128 + (e4 & 127));
    ((float4*)out)[i] = make_float4(a.x + b.x + bb.x, a.y + b.y + bb.y,
                                    a.z + b.z + bb.z, a.w + b.w + bb.w);
}

// ---------------------------------------------------------------------------
extern "C" void kernel_launch(void* const* d_in, const int* in_sizes, int n_in,
                              void* d_out, int out_size)
{
    const float* inputs = (const float*)d_in[0];
    const int*   sel_s  = (const int*)d_in[1];
    const int*   sel_d  = (const int*)d_in[2];
    const float* Ws1 = (const float*)d_in[3];
    const float* bs1 = (const float*)d_in[4];
    const float* Ws2 = (const float*)d_in[5];
    const float* bs2 = (const float*)d_in[6];
    const float* Wd1 = (const float*)d_in[7];
    const float* bd1 = (const float*)d_in[8];
    const float* Wd2 = (const float*)d_in[9];
    const float* bd2 = (const float*)d_in[10];
    float* out = (float*)d_out;

    void* p;
    f16 *inq, *y1, *y2, *y3, *w1, *w2, *w3, *w4;
    float* p4;
    cudaGetSymbolAddress(&p, g_inq); inq = (f16*)p;
    cudaGetSymbolAddress(&p, g_y1);  y1  = (f16*)p;
    cudaGetSymbolAddress(&p, g_y2);  y2  = (f16*)p;
    cudaGetSymbolAddress(&p, g_y3);  y3  = (f16*)p;
    cudaGetSymbolAddress(&p, g_p4);  p4  = (float*)p;
    cudaGetSymbolAddress(&p, g_w1);  w1  = (f16*)p;
    cudaGetSymbolAddress(&p, g_w2);  w2  = (f16*)p;
    cudaGetSymbolAddress(&p, g_w3);  w3  = (f16*)p;
    cudaGetSymbolAddress(&p, g_w4);  w4  = (f16*)p;

    const int SMEM_BYTES = 1024 + 3 * 32768;   // 99328
    // Three distinct instantiations (L1 and L3 share one); each needs opt-in.
    cudaFuncSetAttribute(gemm_mma_kernel<256, 256, 512, true,  1>,
                         cudaFuncAttributeMaxDynamicSharedMemorySize, SMEM_BYTES);
    cudaFuncSetAttribute(gemm_mma_kernel<512, 512, 256, true,  1>,
                         cudaFuncAttributeMaxDynamicSharedMemorySize, SMEM_BYTES);
    cudaFuncSetAttribute(gemm_mma_kernel<256, 512, 128, false, 2>,
                         cudaFuncAttributeMaxDynamicSharedMemorySize, SMEM_BYTES);

    prep_kernel<<<dim3(32, 5, 8), 256>>>(Ws1, Ws2, Wd1, Wd2, inputs, sel_s, sel_d,
                                         w1, w2, w3, w4, inq);

    dim3 blk(256);
    gemm_mma_kernel<256, 256, 512, true,  1><<<dim3(4, 16, 8), blk, SMEM_BYTES>>>(
        inq, w1, bs1, nullptr, y1, sel_s);
    gemm_mma_kernel<512, 512, 256, true,  1><<<dim3(2, 16, 8), blk, SMEM_BYTES>>>(
        y1, w2, bs2, nullptr, y2, sel_s);
    gemm_mma_kernel<256, 256, 512, true,  1><<<dim3(4, 16, 8), blk, SMEM_BYTES>>>(
        y2, w3, bd1, nullptr, y3, sel_d);
    // L4: split-K x2 -> raw partials, then deterministic reduce (+bias)
    gemm_mma_kernel<256, 512, 128, false, 2><<<dim3(2, 16, 8), blk, SMEM_BYTES>>>(
        y3, w4, bd2, p4, nullptr, sel_d);
    reduce4_kernel<<<2048, 256>>>(p4, bd2, sel_d, out);
}